// round 16
// baseline (speedup 1.0000x reference)
#include <cuda_runtime.h>
#include <cuda.h>
#include <cuda_fp16.h>
#include <cstdint>

// ============================================================================
// Problem constants — 12-warp pipeline, 4-stage BK=64 ring, flat frag prefetch
// ============================================================================
#define DIN    4096
#define DOUT   12288
#define MROWS  4096

#define BM     256              // 4 warp-rows x 64
#define BN     192              // 3 warp-cols x 64
#define BK     64               // halves per stage = 128B rows
#define KT     64               // DIN / BK
#define STAGES 4

#define NTILES 1024             // column-major: t -> (m = t & 15, n = t >> 4)

#define GRID        152
#define FULL_UNITS  912         // 152 * 6
#define REM_TILES   112
#define REM_CHUNKS  8
#define REM_KT      8           // stages per chunk
#define TOTAL_UNITS (FULL_UNITS + REM_TILES * REM_CHUNKS)   // 1808

#define A_BYTES     (BM * 128)              // 32768
#define B_BYTES     (BN * 128)              // 24576
#define STAGE_BYTES (A_BYTES + B_BYTES)     // 57344
#define SMEM_DATA0  1024
#define SMEM_TOTAL  (SMEM_DATA0 + STAGES * STAGE_BYTES)   // 230400 (launch-proven)

#define MBAR_FULL(s)  ((s) * 16)
#define CTRL_CNT      64                    // 4 ints: per-slot arrive counters
#define CTRL_GNEXT    96                    // 4 ints: per-slot next stage seq

#define NWARPS   12
#define NTHREADS 384

// ============================================================================
// Scratch: fp16 operands (dequantized W, converted X)
// ============================================================================
__device__ __half g_W16[(size_t)DOUT * DIN];   // 96 MB
__device__ __half g_X16[(size_t)MROWS * DIN];  // 32 MB

// ============================================================================
// PTX helpers
// ============================================================================
__device__ __forceinline__ uint32_t smem_u32(const void* p) {
    uint32_t a;
    asm("{ .reg .u64 t; cvta.to.shared.u64 t, %1; cvt.u32.u64 %0, t; }" : "=r"(a) : "l"(p));
    return a;
}

#define MBAR_INIT(addr, cnt) \
    asm volatile("mbarrier.init.shared.b64 [%0], %1;" :: "r"(addr), "r"(cnt) : "memory")
#define MBAR_EXPECT_TX(addr, bytes) \
    asm volatile("mbarrier.arrive.expect_tx.shared.b64 _, [%0], %1;" :: "r"(addr), "r"(bytes) : "memory")
#define MBAR_ARRIVE(addr) \
    asm volatile("mbarrier.arrive.shared.b64 _, [%0];" :: "r"(addr) : "memory")

#define MBAR_WAIT(mbar_addr, phase_parity) do {                                         \
    uint32_t _mbar = (uint32_t)(mbar_addr);                                             \
    uint32_t _par  = (uint32_t)(phase_parity);                                          \
    uint32_t _done;                                                                     \
    asm volatile("{\n\t.reg .pred p;\n\t"                                               \
        "mbarrier.try_wait.parity.acquire.cta.shared::cta.b64 p, [%1], %2;\n\t"         \
        "selp.b32 %0, 1, 0, p;\n\t}"                                                    \
        : "=r"(_done) : "r"(_mbar), "r"(_par) : "memory");                              \
    if (!_done) {                                                                       \
        asm volatile("{\n\t.reg .pred P1;\n\t"                                          \
            "WAIT_LOOP_%=:\n\t"                                                         \
            "mbarrier.try_wait.parity.acquire.cta.shared::cta.b64 P1, [%0], %1, 0x989680;\n\t" \
            "@P1 bra.uni WAIT_DONE_%=;\n\t"                                             \
            "bra.uni WAIT_LOOP_%=;\n\t"                                                 \
            "WAIT_DONE_%=:\n\t}"                                                        \
            :: "r"(_mbar), "r"(_par) : "memory");                                       \
    }                                                                                   \
} while (0)

#define TMA_LOAD2D(smem, map, cx, cy, mbar)                                             \
    asm volatile("cp.async.bulk.tensor.2d.shared::cta.global.tile.mbarrier::complete_tx::bytes " \
                 "[%0], [%1, {%2, %3}], [%4];"                                          \
                 :: "r"(smem), "l"(map), "r"(cx), "r"(cy), "r"(mbar) : "memory")

#define LDSM_X4(r0, r1, r2, r3, addr)                                                   \
    asm volatile("ldmatrix.sync.aligned.m8n8.x4.shared.b16 {%0,%1,%2,%3}, [%4];"        \
                 : "=r"(r0), "=r"(r1), "=r"(r2), "=r"(r3) : "r"(addr))

__device__ __forceinline__ void mma_f16(float c[4], uint32_t a0, uint32_t a1, uint32_t a2,
                                        uint32_t a3, uint32_t b0, uint32_t b1) {
    asm volatile(
        "mma.sync.aligned.m16n8k16.row.col.f32.f16.f16.f32 "
        "{%0,%1,%2,%3}, {%4,%5,%6,%7}, {%8,%9}, {%0,%1,%2,%3};"
        : "+f"(c[0]), "+f"(c[1]), "+f"(c[2]), "+f"(c[3])
        : "r"(a0), "r"(a1), "r"(a2), "r"(a3), "r"(b0), "r"(b1));
}

// ============================================================================
// Merged prep: dequant W -> fp16, convert X -> fp16, zero split-K out strip
// ============================================================================
__device__ __forceinline__ uint32_t h2bits(float a, float b) {
    __half2 h = __floats2half2_rn(a, b);
    return *reinterpret_cast<uint32_t*>(&h);
}

#define W_BLOCKS ((DOUT * DIN / 8) / 256)   // 24576
#define X_BLOCKS ((MROWS * DIN / 8) / 256)  // 8192
#define REM_COL0  10944
#define REM_COLS  1344
#define Z_BLOCKS  ((MROWS * REM_COLS / 4) / 256)   // 5376

__global__ void prep_kernel(const float4* __restrict__ x, const float4* __restrict__ peso,
                            const float* __restrict__ escala,
                            uint4* __restrict__ gX, uint4* __restrict__ gW,
                            float* __restrict__ out) {
    const int bid = blockIdx.x;
    if (bid < W_BLOCKS) {
        int i = bid * 256 + threadIdx.x;
        int e   = i << 3;
        int row = e >> 12;
        int col = e & (DIN - 1);
        float s = __ldg(&escala[(row >> 7) * (DIN / 128) + (col >> 7)]);
        float4 v0 = peso[2 * i], v1 = peso[2 * i + 1];
        uint4 u;
        u.x = h2bits(v0.x * s, v0.y * s); u.y = h2bits(v0.z * s, v0.w * s);
        u.z = h2bits(v1.x * s, v1.y * s); u.w = h2bits(v1.z * s, v1.w * s);
        gW[i] = u;
    } else if (bid < W_BLOCKS + X_BLOCKS) {
        int i = (bid - W_BLOCKS) * 256 + threadIdx.x;
        float4 v0 = x[2 * i], v1 = x[2 * i + 1];
        uint4 u;
        u.x = h2bits(v0.x, v0.y); u.y = h2bits(v0.z, v0.w);
        u.z = h2bits(v1.x, v1.y); u.w = h2bits(v1.z, v1.w);
        gX[i] = u;
    } else {
        int i = (bid - W_BLOCKS - X_BLOCKS) * 256 + threadIdx.x;
        int row = i / (REM_COLS / 4);
        int c4  = i % (REM_COLS / 4);
        *reinterpret_cast<float4*>(&out[(size_t)row * DOUT + REM_COL0 + c4 * 4]) =
            make_float4(0.f, 0.f, 0.f, 0.f);
    }
}

// ============================================================================
// GEMM: C[m,n] = sum_k X[m,k] * W[n,k]   (fp16 in, fp32 accum/out)
//   Flat fragment prefetch: stage-top waits the NEXT slot's FULL (current was
//   waited one stage earlier); the ks==3 step loads frags(0) from the NEXT
//   ring slot (compile-time address, no wait in body). Each stage starts with
//   its first fragments already in registers -> no post-barrier LDS burst.
//   All waits outside the unrolled body (R10 lesson).
// ============================================================================
__global__ void __launch_bounds__(NTHREADS, 1)
gemm_f16_kernel(const __grid_constant__ CUtensorMap tmA,
                const __grid_constant__ CUtensorMap tmB,
                float* __restrict__ out) {
    extern __shared__ char smem[];
    const uint32_t sb = smem_u32(smem);
    int* scnt = reinterpret_cast<int*>(smem + CTRL_CNT);
    int* sgn  = reinterpret_cast<int*>(smem + CTRL_GNEXT);
    const int tid  = threadIdx.x;
    const int wid  = tid >> 5;
    const int lane = tid & 31;
    const int b    = blockIdx.x;

    const int nch  = (b < 136) ? 6 : 5;          // chunk units this CTA (896=152*5+136)
    const int stot = 384 + REM_KT * nch;         // total stages this CTA

    auto stage_coords = [&](int gq, int& t, int& kt) {
        if (gq < 384) {
            t  = b + 152 * (gq >> 6);
            kt = gq & 63;
        } else {
            int h = gq - 384;
            int u = FULL_UNITS + b + 152 * (h >> 3);
            int r = u - FULL_UNITS;
            t  = FULL_UNITS + (r >> 3);
            kt = ((r & 7) << 3) + (h & 7);
        }
    };

    // gq >= stot: dummy arrive (completes the final next-wait; no TMA)
    auto load_stage = [&](int gq, int slot) {
        if (gq >= stot) { MBAR_ARRIVE(sb + MBAR_FULL(slot)); return; }
        int t, kt;
        stage_coords(gq, t, kt);
        const int m0 = (t & 15) * BM;
        const int n0 = (t >> 4) * BN;
        const int k0 = kt * BK;
        const uint32_t stg = sb + SMEM_DATA0 + slot * STAGE_BYTES;
        MBAR_EXPECT_TX(sb + MBAR_FULL(slot), STAGE_BYTES);
        TMA_LOAD2D(stg,           &tmA, k0, m0, sb + MBAR_FULL(slot));
        TMA_LOAD2D(stg + A_BYTES, &tmB, k0, n0, sb + MBAR_FULL(slot));
    };

    if (tid == 0) {
        for (int s = 0; s < STAGES; s++) {
            MBAR_INIT(sb + MBAR_FULL(s), 1);
            scnt[s] = 0;
            sgn[s]  = s + STAGES;
        }
    }
    __syncthreads();
    if (tid == 0) {                // prologue: fill all 4 slots
        load_stage(0, 0); load_stage(1, 1);
        load_stage(2, 2); load_stage(3, 3);
    }

    // ---------------- compute warps: 4M x 3N grid, warp tile 64x64 ----------------
    const int warp_m = wid & 3;
    const int warp_n = wid >> 2;
    const int q  = lane >> 3;
    const int iq = lane & 7;

    const int a_rif  = ((q & 1) << 3) + iq;
    const uint32_t a_csel = (uint32_t)(q >> 1);
    const int b_rif  = ((q >> 1) << 3) + iq;
    const uint32_t b_csel = (uint32_t)(q & 1);

    uint32_t a_off[4], b_off[4];
#pragma unroll
    for (int mf = 0; mf < 4; mf++)
        a_off[mf] = (uint32_t)((warp_m * 64 + mf * 16 + a_rif) * 128);
#pragma unroll
    for (int p = 0; p < 4; p++)
        b_off[p] = (uint32_t)((warp_n * 64 + p * 16 + b_rif) * 128);

    uint32_t a[2][4][4], bfr[2][8][2];

    auto load_frags = [&](int ks, uint32_t (&af)[4][4], uint32_t (&bf)[8][2],
                          uint32_t As, uint32_t Bs) {
        const uint32_t xa = (((uint32_t)(2 * ks) + a_csel) ^ (uint32_t)iq) << 4;
        const uint32_t xb = (((uint32_t)(2 * ks) + b_csel) ^ (uint32_t)iq) << 4;
#pragma unroll
        for (int mf = 0; mf < 4; mf++)
            LDSM_X4(af[mf][0], af[mf][1], af[mf][2], af[mf][3], As + a_off[mf] + xa);
#pragma unroll
        for (int p = 0; p < 4; p++)
            LDSM_X4(bf[2 * p][0], bf[2 * p][1], bf[2 * p + 1][0], bf[2 * p + 1][1],
                    Bs + b_off[p] + xb);
    };

    const int g2l = lane >> 2;
    const int tig = lane & 3;

    // flat-pipeline prologue: wait slot 0, preload its frags(0)
    int s = 0, ph = 0;
    MBAR_WAIT(sb + MBAR_FULL(0), 0);
    load_frags(0, a[0], bfr[0], sb + SMEM_DATA0, sb + SMEM_DATA0 + A_BYTES);

    for (int u = b; u < TOTAL_UNITS; u += GRID) {
        int t, nkt;
        const bool full = (u < FULL_UNITS);
        if (full) { t = u; nkt = KT; }
        else {
            int r = u - FULL_UNITS;
            t = FULL_UNITS + (r >> 3);
            nkt = REM_KT;
        }
        const int m0 = (t & 15) * BM;
        const int n0 = (t >> 4) * BN;

        float c[4][8][4];
#pragma unroll
        for (int mf = 0; mf < 4; mf++)
#pragma unroll
            for (int nf = 0; nf < 8; nf++)
#pragma unroll
                for (int r = 0; r < 4; r++) c[mf][nf][r] = 0.0f;

        for (int kt = 0; kt < nkt; kt++) {
            // wait NEXT slot's FULL (current slot's was waited one stage ago)
            const int ns  = (s == STAGES - 1) ? 0 : s + 1;
            const int nph = (s == STAGES - 1) ? (ph ^ 1) : ph;
            MBAR_WAIT(sb + MBAR_FULL(ns), nph);

            const uint32_t As  = sb + SMEM_DATA0 + s * STAGE_BYTES;
            const uint32_t Bs  = As + A_BYTES;
            const uint32_t nAs = sb + SMEM_DATA0 + ns * STAGE_BYTES;
            const uint32_t nBs = nAs + A_BYTES;

#pragma unroll
            for (int ks = 0; ks < 4; ks++) {       // frags(0) already in buf 0
                if (ks < 3) load_frags(ks + 1, a[(ks + 1) & 1], bfr[(ks + 1) & 1], As, Bs);
                else        load_frags(0, a[0], bfr[0], nAs, nBs);   // next-slot prefetch
                uint32_t (&af)[4][4] = a[ks & 1];
                uint32_t (&bf)[8][2] = bfr[ks & 1];
#pragma unroll
                for (int mf = 0; mf < 4; mf++)
#pragma unroll
                    for (int nf = 0; nf < 8; nf++)
                        mma_f16(c[mf][nf], af[mf][0], af[mf][1], af[mf][2], af[mf][3],
                                bf[nf][0], bf[nf][1]);
            }
            // Safe point: this stage's LDSM results all consumed by mma.sync.
            __syncwarp();
            if (lane == 0) {
                int my = atomicAdd(&scnt[s], 1);
                if ((my % NWARPS) == NWARPS - 1) {     // last warp: reload this slot
                    int gq = sgn[s];
                    sgn[s] = gq + STAGES;
                    load_stage(gq, s);
                }
            }
            s = ns; ph = nph;
        }

        // ---- epilogue ----
        if (full) {
#pragma unroll
            for (int mf = 0; mf < 4; mf++) {
                const int m = m0 + warp_m * 64 + mf * 16 + g2l;
#pragma unroll
                for (int nf = 0; nf < 8; nf++) {
                    const int n = n0 + warp_n * 64 + nf * 8 + tig * 2;
                    __stwt(reinterpret_cast<float2*>(&out[(size_t)m * DOUT + n]),
                           make_float2(c[mf][nf][0], c[mf][nf][1]));
                    __stwt(reinterpret_cast<float2*>(&out[(size_t)(m + 8) * DOUT + n]),
                           make_float2(c[mf][nf][2], c[mf][nf][3]));
                }
            }
        } else {
#pragma unroll
            for (int mf = 0; mf < 4; mf++) {
                const int m = m0 + warp_m * 64 + mf * 16 + g2l;
#pragma unroll
                for (int nf = 0; nf < 8; nf++) {
                    const int n = n0 + warp_n * 64 + nf * 8 + tig * 2;
                    atomicAdd(&out[(size_t)m * DOUT + n],           c[mf][nf][0]);
                    atomicAdd(&out[(size_t)m * DOUT + n + 1],       c[mf][nf][1]);
                    atomicAdd(&out[(size_t)(m + 8) * DOUT + n],     c[mf][nf][2]);
                    atomicAdd(&out[(size_t)(m + 8) * DOUT + n + 1], c[mf][nf][3]);
                }
            }
        }
    }
}

// ============================================================================
// Host launch
// ============================================================================
typedef CUresult (*PFN_encodeTiled)(CUtensorMap*, CUtensorMapDataType, cuuint32_t, void*,
                                    const cuuint64_t*, const cuuint64_t*, const cuuint32_t*,
                                    const cuuint32_t*, CUtensorMapInterleave, CUtensorMapSwizzle,
                                    CUtensorMapL2promotion, CUtensorMapFloatOOBfill);

static PFN_encodeTiled get_encode_fn() {
    void* fn = nullptr;
#if CUDART_VERSION >= 12050
    cudaDriverEntryPointQueryResult qr;
    cudaGetDriverEntryPointByVersion("cuTensorMapEncodeTiled", &fn, 12000, cudaEnableDefault, &qr);
#else
    cudaGetDriverEntryPoint("cuTensorMapEncodeTiled", &fn, cudaEnableDefault);
#endif
    return (PFN_encodeTiled)fn;
}

static void encode_2d_f16(PFN_encodeTiled enc, CUtensorMap* tm, void* ptr,
                          uint64_t d0, uint64_t d1, uint32_t b0, uint32_t b1) {
    cuuint64_t dims[2]    = {d0, d1};
    cuuint64_t strides[1] = {d0 * sizeof(__half)};
    cuuint32_t box[2]     = {b0, b1};
    cuuint32_t es[2]      = {1, 1};
    enc(tm, CU_TENSOR_MAP_DATA_TYPE_FLOAT16, 2, ptr, dims, strides, box, es,
        CU_TENSOR_MAP_INTERLEAVE_NONE, CU_TENSOR_MAP_SWIZZLE_128B,
        CU_TENSOR_MAP_L2_PROMOTION_L2_128B, CU_TENSOR_MAP_FLOAT_OOB_FILL_NONE);
}

extern "C" void kernel_launch(void* const* d_in, const int* in_sizes, int n_in,
                              void* d_out, int out_size) {
    const float* x      = (const float*)d_in[0];
    const float* peso   = (const float*)d_in[1];
    const float* escala = (const float*)d_in[2];
    float* out          = (float*)d_out;

    __half *gX = nullptr, *gW = nullptr;
    cudaGetSymbolAddress((void**)&gX, g_X16);
    cudaGetSymbolAddress((void**)&gW, g_W16);

    prep_kernel<<<W_BLOCKS + X_BLOCKS + Z_BLOCKS, 256>>>(
        (const float4*)x, (const float4*)peso, escala, (uint4*)gX, (uint4*)gW, out);

    PFN_encodeTiled enc = get_encode_fn();
    CUtensorMap tmA, tmB;
    encode_2d_f16(enc, &tmA, gX, DIN, MROWS, BK, BM);   // box 64x256
    encode_2d_f16(enc, &tmB, gW, DIN, DOUT,  BK, BN);   // box 64x192

    static bool attr_set = false;
    if (!attr_set) {
        cudaFuncSetAttribute(gemm_f16_kernel, cudaFuncAttributeMaxDynamicSharedMemorySize,
                             SMEM_TOTAL);
        attr_set = true;
    }

    gemm_f16_kernel<<<GRID, NTHREADS, SMEM_TOTAL>>>(tmA, tmB, out);
}

// round 17
// speedup vs baseline: 2.8948x; 2.8948x over previous
#include <cuda_runtime.h>
#include <cuda.h>
#include <cuda_fp16.h>
#include <cstdint>

// ============================================================================
// Problem constants — R14 structure (best: 866.3us), micro-tuned
// ============================================================================
#define DIN    4096
#define DOUT   12288
#define MROWS  4096

#define BM     256              // 4 warp-rows x 64
#define BN     192              // 3 warp-cols x 64
#define BK     128              // halves per stage (2 slabs of 64)
#define KT     32               // DIN / BK

#define NTILES 1024             // column-major: t -> (m = t & 15, n = t >> 4)

#define GRID        152
#define FULL_UNITS  912         // 152 * 6
#define REM_TILES   112
#define REM_CHUNKS  8
#define REM_KT      4           // KT / REM_CHUNKS
#define TOTAL_UNITS (FULL_UNITS + REM_TILES * REM_CHUNKS)   // 1808

#define A_SLAB      (BM * 128)              // 32768
#define B_SLAB      (BN * 128)              // 24576
#define A_BYTES     (2 * A_SLAB)            // 65536
#define B_BYTES     (2 * B_SLAB)            // 49152
#define STAGE_BYTES (A_BYTES + B_BYTES)     // 114688
#define SMEM_DATA0  1024
#define SMEM_TOTAL  (SMEM_DATA0 + 2 * STAGE_BYTES)   // 230400 (launch-proven)

#define MBAR_FULL(s)  ((s) * 16)
#define CTRL_CNT      64
#define CTRL_GNEXT    80

#define NWARPS   12
#define NTHREADS 384

// ============================================================================
// Scratch: fp16 operands (dequantized W, converted X)
// ============================================================================
__device__ __half g_W16[(size_t)DOUT * DIN];   // 96 MB
__device__ __half g_X16[(size_t)MROWS * DIN];  // 32 MB

// ============================================================================
// PTX helpers
// ============================================================================
__device__ __forceinline__ uint32_t smem_u32(const void* p) {
    uint32_t a;
    asm("{ .reg .u64 t; cvta.to.shared.u64 t, %1; cvt.u32.u64 %0, t; }" : "=r"(a) : "l"(p));
    return a;
}

#define MBAR_INIT(addr, cnt) \
    asm volatile("mbarrier.init.shared.b64 [%0], %1;" :: "r"(addr), "r"(cnt) : "memory")
#define MBAR_EXPECT_TX(addr, bytes) \
    asm volatile("mbarrier.arrive.expect_tx.shared.b64 _, [%0], %1;" :: "r"(addr), "r"(bytes) : "memory")

#define MBAR_WAIT(mbar_addr, phase_parity) do {                                         \
    uint32_t _mbar = (uint32_t)(mbar_addr);                                             \
    uint32_t _par  = (uint32_t)(phase_parity);                                          \
    uint32_t _done;                                                                     \
    asm volatile("{\n\t.reg .pred p;\n\t"                                               \
        "mbarrier.try_wait.parity.acquire.cta.shared::cta.b64 p, [%1], %2;\n\t"         \
        "selp.b32 %0, 1, 0, p;\n\t}"                                                    \
        : "=r"(_done) : "r"(_mbar), "r"(_par) : "memory");                              \
    if (!_done) {                                                                       \
        asm volatile("{\n\t.reg .pred P1;\n\t"                                          \
            "WAIT_LOOP_%=:\n\t"                                                         \
            "mbarrier.try_wait.parity.acquire.cta.shared::cta.b64 P1, [%0], %1, 0x989680;\n\t" \
            "@P1 bra.uni WAIT_DONE_%=;\n\t"                                             \
            "bra.uni WAIT_LOOP_%=;\n\t"                                                 \
            "WAIT_DONE_%=:\n\t}"                                                        \
            :: "r"(_mbar), "r"(_par) : "memory");                                       \
    }                                                                                   \
} while (0)

#define TMA_LOAD2D(smem, map, cx, cy, mbar)                                             \
    asm volatile("cp.async.bulk.tensor.2d.shared::cta.global.tile.mbarrier::complete_tx::bytes " \
                 "[%0], [%1, {%2, %3}], [%4];"                                          \
                 :: "r"(smem), "l"(map), "r"(cx), "r"(cy), "r"(mbar) : "memory")

#define LDSM_X4(r0, r1, r2, r3, addr)                                                   \
    asm volatile("ldmatrix.sync.aligned.m8n8.x4.shared.b16 {%0,%1,%2,%3}, [%4];"        \
                 : "=r"(r0), "=r"(r1), "=r"(r2), "=r"(r3) : "r"(addr))

__device__ __forceinline__ void mma_f16(float c[4], uint32_t a0, uint32_t a1, uint32_t a2,
                                        uint32_t a3, uint32_t b0, uint32_t b1) {
    asm volatile(
        "mma.sync.aligned.m16n8k16.row.col.f32.f16.f16.f32 "
        "{%0,%1,%2,%3}, {%4,%5,%6,%7}, {%8,%9}, {%0,%1,%2,%3};"
        : "+f"(c[0]), "+f"(c[1]), "+f"(c[2]), "+f"(c[3])
        : "r"(a0), "r"(a1), "r"(a2), "r"(a3), "r"(b0), "r"(b1));
}

// ============================================================================
// Merged prep: dequant W -> fp16, convert X -> fp16, zero split-K out strip.
// 16 floats/thread (deeper MLP), streaming stores (__stcs: evict-first).
// ============================================================================
__device__ __forceinline__ uint32_t h2bits(float a, float b) {
    __half2 h = __floats2half2_rn(a, b);
    return *reinterpret_cast<uint32_t*>(&h);
}

#define W_BLOCKS ((DOUT * DIN / 16) / 256)   // 12288
#define X_BLOCKS ((MROWS * DIN / 16) / 256)  // 4096
#define REM_COL0  10944                      // (912 >> 4) * 192
#define REM_COLS  1344
#define Z_BLOCKS  ((MROWS * REM_COLS / 4) / 256)   // 5376

__global__ void prep_kernel(const float4* __restrict__ x, const float4* __restrict__ peso,
                            const float* __restrict__ escala,
                            uint4* __restrict__ gX, uint4* __restrict__ gW,
                            float* __restrict__ out) {
    const int bid = blockIdx.x;
    if (bid < W_BLOCKS) {
        int i = bid * 256 + threadIdx.x;     // 16-float unit index
        int e   = i << 4;                    // first element
        int row = e >> 12;                   // / DIN
        int col = e & (DIN - 1);             // multiple of 16 -> one scale block
        float s = __ldg(&escala[(row >> 7) * (DIN / 128) + (col >> 7)]);
        float4 v0 = peso[4 * i],     v1 = peso[4 * i + 1];
        float4 v2 = peso[4 * i + 2], v3 = peso[4 * i + 3];
        uint4 u0, u1;
        u0.x = h2bits(v0.x * s, v0.y * s); u0.y = h2bits(v0.z * s, v0.w * s);
        u0.z = h2bits(v1.x * s, v1.y * s); u0.w = h2bits(v1.z * s, v1.w * s);
        u1.x = h2bits(v2.x * s, v2.y * s); u1.y = h2bits(v2.z * s, v2.w * s);
        u1.z = h2bits(v3.x * s, v3.y * s); u1.w = h2bits(v3.z * s, v3.w * s);
        __stcs(&gW[2 * i],     u0);
        __stcs(&gW[2 * i + 1], u1);
    } else if (bid < W_BLOCKS + X_BLOCKS) {
        int i = (bid - W_BLOCKS) * 256 + threadIdx.x;
        float4 v0 = x[4 * i],     v1 = x[4 * i + 1];
        float4 v2 = x[4 * i + 2], v3 = x[4 * i + 3];
        uint4 u0, u1;
        u0.x = h2bits(v0.x, v0.y); u0.y = h2bits(v0.z, v0.w);
        u0.z = h2bits(v1.x, v1.y); u0.w = h2bits(v1.z, v1.w);
        u1.x = h2bits(v2.x, v2.y); u1.y = h2bits(v2.z, v2.w);
        u1.z = h2bits(v3.x, v3.y); u1.w = h2bits(v3.z, v3.w);
        __stcs(&gX[2 * i],     u0);
        __stcs(&gX[2 * i + 1], u1);
    } else {
        int i = (bid - W_BLOCKS - X_BLOCKS) * 256 + threadIdx.x;   // float4 index
        int row = i / (REM_COLS / 4);
        int c4  = i % (REM_COLS / 4);
        *reinterpret_cast<float4*>(&out[(size_t)row * DOUT + REM_COL0 + c4 * 4]) =
            make_float4(0.f, 0.f, 0.f, 0.f);
    }
}

// ============================================================================
// GEMM: C[m,n] = sum_k X[m,k] * W[n,k]   (fp16 in, fp32 accum/out)
//   R14 structure: producer-less 12-warp pipeline, CTA 256x192, 2-stage ring
//   (112KB/stage). Last-arriving warp (atomic counter) reloads the slot.
//   Redundant __syncwarp before the trigger removed (mma.sync.aligned leaves
//   the warp converged). Hot loop body identical to R14.
// ============================================================================
__global__ void __launch_bounds__(NTHREADS, 1)
gemm_f16_kernel(const __grid_constant__ CUtensorMap tmA,
                const __grid_constant__ CUtensorMap tmB,
                float* __restrict__ out) {
    extern __shared__ char smem[];
    const uint32_t sb = smem_u32(smem);
    int* scnt = reinterpret_cast<int*>(smem + CTRL_CNT);
    int* sgn  = reinterpret_cast<int*>(smem + CTRL_GNEXT);
    const int tid  = threadIdx.x;
    const int wid  = tid >> 5;
    const int lane = tid & 31;
    const int b    = blockIdx.x;

    const int nch  = (b < 136) ? 6 : 5;          // chunk units this CTA (896=152*5+136)
    const int stot = 192 + 4 * nch;              // total stages this CTA

    auto stage_coords = [&](int gq, int& t, int& kt) {
        if (gq < 192) {
            t  = b + 152 * (gq >> 5);
            kt = gq & 31;
        } else {
            int h = gq - 192;
            int u = FULL_UNITS + b + 152 * (h >> 2);
            int r = u - FULL_UNITS;
            t  = FULL_UNITS + (r >> 3);
            kt = ((r & 7) << 2) + (h & 3);
        }
    };

    auto load_stage = [&](int gq, int slot) {
        int t, kt;
        stage_coords(gq, t, kt);
        const int m0 = (t & 15) * BM;
        const int n0 = (t >> 4) * BN;
        const int k0 = kt * BK;
        const uint32_t stg = sb + SMEM_DATA0 + slot * STAGE_BYTES;
        MBAR_EXPECT_TX(sb + MBAR_FULL(slot), STAGE_BYTES);
        TMA_LOAD2D(stg,                    &tmA, k0,      m0, sb + MBAR_FULL(slot));
        TMA_LOAD2D(stg + A_SLAB,           &tmA, k0 + 64, m0, sb + MBAR_FULL(slot));
        TMA_LOAD2D(stg + A_BYTES,          &tmB, k0,      n0, sb + MBAR_FULL(slot));
        TMA_LOAD2D(stg + A_BYTES + B_SLAB, &tmB, k0 + 64, n0, sb + MBAR_FULL(slot));
    };

    if (tid == 0) {
        MBAR_INIT(sb + MBAR_FULL(0), 1);
        MBAR_INIT(sb + MBAR_FULL(1), 1);
        scnt[0] = 0; scnt[1] = 0;
        sgn[0] = 2;  sgn[1] = 3;
    }
    __syncthreads();
    if (tid == 0) {                // prologue: fill both slots
        load_stage(0, 0);
        load_stage(1, 1);
    }

    // ---------------- compute warps: 4M x 3N grid, warp tile 64x64 ----------------
    const int warp_m = wid & 3;
    const int warp_n = wid >> 2;
    const int q  = lane >> 3;
    const int iq = lane & 7;

    const int a_rif  = ((q & 1) << 3) + iq;
    const uint32_t a_csel = (uint32_t)(q >> 1);
    const int b_rif  = ((q >> 1) << 3) + iq;
    const uint32_t b_csel = (uint32_t)(q & 1);

    uint32_t a_off[4], b_off[4];
#pragma unroll
    for (int mf = 0; mf < 4; mf++)
        a_off[mf] = (uint32_t)((warp_m * 64 + mf * 16 + a_rif) * 128);
#pragma unroll
    for (int p = 0; p < 4; p++)
        b_off[p] = (uint32_t)((warp_n * 64 + p * 16 + b_rif) * 128);

    uint32_t a[2][4][4], bfr[2][8][2];

    auto load_frags = [&](int ks, uint32_t (&af)[4][4], uint32_t (&bf)[8][2],
                          uint32_t As, uint32_t Bs) {
        const uint32_t cha = (uint32_t)(2 * ks) + a_csel;
        const uint32_t chb = (uint32_t)(2 * ks) + b_csel;
        const uint32_t baseA = As + (cha >> 3) * A_SLAB + (((cha & 7u) ^ (uint32_t)iq) << 4);
        const uint32_t baseB = Bs + (chb >> 3) * B_SLAB + (((chb & 7u) ^ (uint32_t)iq) << 4);
#pragma unroll
        for (int mf = 0; mf < 4; mf++)
            LDSM_X4(af[mf][0], af[mf][1], af[mf][2], af[mf][3], baseA + a_off[mf]);
#pragma unroll
        for (int p = 0; p < 4; p++)
            LDSM_X4(bf[2 * p][0], bf[2 * p][1], bf[2 * p + 1][0], bf[2 * p + 1][1],
                    baseB + b_off[p]);
    };

    const int g2l = lane >> 2;
    const int tig = lane & 3;

    int s = 0, ph = 0;                    // ring state persists across units
    for (int u = b; u < TOTAL_UNITS; u += GRID) {
        int t, kt0, kt1;
        const bool full = (u < FULL_UNITS);
        if (full) { t = u; kt0 = 0; kt1 = KT; }
        else {
            int r = u - FULL_UNITS;
            t = FULL_UNITS + (r >> 3);
            kt0 = (r & 7) * REM_KT; kt1 = kt0 + REM_KT;
        }
        const int m0 = (t & 15) * BM;
        const int n0 = (t >> 4) * BN;

        float c[4][8][4];
#pragma unroll
        for (int mf = 0; mf < 4; mf++)
#pragma unroll
            for (int nf = 0; nf < 8; nf++)
#pragma unroll
                for (int r = 0; r < 4; r++) c[mf][nf][r] = 0.0f;

        for (int kt = kt0; kt < kt1; kt++) {
            MBAR_WAIT(sb + MBAR_FULL(s), ph);
            const uint32_t As = sb + SMEM_DATA0 + s * STAGE_BYTES;
            const uint32_t Bs = As + A_BYTES;

            load_frags(0, a[0], bfr[0], As, Bs);
#pragma unroll
            for (int ks = 0; ks < 8; ks++) {
                if (ks < 7) load_frags(ks + 1, a[(ks + 1) & 1], bfr[(ks + 1) & 1], As, Bs);
                uint32_t (&af)[4][4] = a[ks & 1];
                uint32_t (&bf)[8][2] = bfr[ks & 1];
#pragma unroll
                for (int mf = 0; mf < 4; mf++)
#pragma unroll
                    for (int nf = 0; nf < 8; nf++)
                        mma_f16(c[mf][nf], af[mf][0], af[mf][1], af[mf][2], af[mf][3],
                                bf[nf][0], bf[nf][1]);
            }
            // Safe point: mma.sync.aligned consumed all this stage's LDSM
            // results and leaves the warp converged (no __syncwarp needed).
            if (lane == 0) {
                int my = atomicAdd(&scnt[s], 1);
                if ((my % NWARPS) == NWARPS - 1) {     // last warp: reload this slot
                    int gq = sgn[s];
                    sgn[s] = gq + 2;
                    if (gq < stot) load_stage(gq, s);
                }
            }
            if (s == 1) { s = 0; ph ^= 1; } else { s = 1; }
        }

        // ---- epilogue ----
        if (full) {
#pragma unroll
            for (int mf = 0; mf < 4; mf++) {
                const int m = m0 + warp_m * 64 + mf * 16 + g2l;
#pragma unroll
                for (int nf = 0; nf < 8; nf++) {
                    const int n = n0 + warp_n * 64 + nf * 8 + tig * 2;
                    __stwt(reinterpret_cast<float2*>(&out[(size_t)m * DOUT + n]),
                           make_float2(c[mf][nf][0], c[mf][nf][1]));
                    __stwt(reinterpret_cast<float2*>(&out[(size_t)(m + 8) * DOUT + n]),
                           make_float2(c[mf][nf][2], c[mf][nf][3]));
                }
            }
        } else {
#pragma unroll
            for (int mf = 0; mf < 4; mf++) {
                const int m = m0 + warp_m * 64 + mf * 16 + g2l;
#pragma unroll
                for (int nf = 0; nf < 8; nf++) {
                    const int n = n0 + warp_n * 64 + nf * 8 + tig * 2;
                    atomicAdd(&out[(size_t)m * DOUT + n],           c[mf][nf][0]);
                    atomicAdd(&out[(size_t)m * DOUT + n + 1],       c[mf][nf][1]);
                    atomicAdd(&out[(size_t)(m + 8) * DOUT + n],     c[mf][nf][2]);
                    atomicAdd(&out[(size_t)(m + 8) * DOUT + n + 1], c[mf][nf][3]);
                }
            }
        }
    }
}

// ============================================================================
// Host launch
// ============================================================================
typedef CUresult (*PFN_encodeTiled)(CUtensorMap*, CUtensorMapDataType, cuuint32_t, void*,
                                    const cuuint64_t*, const cuuint64_t*, const cuuint32_t*,
                                    const cuuint32_t*, CUtensorMapInterleave, CUtensorMapSwizzle,
                                    CUtensorMapL2promotion, CUtensorMapFloatOOBfill);

static PFN_encodeTiled get_encode_fn() {
    void* fn = nullptr;
#if CUDART_VERSION >= 12050
    cudaDriverEntryPointQueryResult qr;
    cudaGetDriverEntryPointByVersion("cuTensorMapEncodeTiled", &fn, 12000, cudaEnableDefault, &qr);
#else
    cudaGetDriverEntryPoint("cuTensorMapEncodeTiled", &fn, cudaEnableDefault);
#endif
    return (PFN_encodeTiled)fn;
}

static void encode_2d_f16(PFN_encodeTiled enc, CUtensorMap* tm, void* ptr,
                          uint64_t d0, uint64_t d1, uint32_t b0, uint32_t b1) {
    cuuint64_t dims[2]    = {d0, d1};
    cuuint64_t strides[1] = {d0 * sizeof(__half)};
    cuuint32_t box[2]     = {b0, b1};
    cuuint32_t es[2]      = {1, 1};
    enc(tm, CU_TENSOR_MAP_DATA_TYPE_FLOAT16, 2, ptr, dims, strides, box, es,
        CU_TENSOR_MAP_INTERLEAVE_NONE, CU_TENSOR_MAP_SWIZZLE_128B,
        CU_TENSOR_MAP_L2_PROMOTION_L2_128B, CU_TENSOR_MAP_FLOAT_OOB_FILL_NONE);
}

extern "C" void kernel_launch(void* const* d_in, const int* in_sizes, int n_in,
                              void* d_out, int out_size) {
    const float* x      = (const float*)d_in[0];
    const float* peso   = (const float*)d_in[1];
    const float* escala = (const float*)d_in[2];
    float* out          = (float*)d_out;

    __half *gX = nullptr, *gW = nullptr;
    cudaGetSymbolAddress((void**)&gX, g_X16);
    cudaGetSymbolAddress((void**)&gW, g_W16);

    prep_kernel<<<W_BLOCKS + X_BLOCKS + Z_BLOCKS, 256>>>(
        (const float4*)x, (const float4*)peso, escala, (uint4*)gX, (uint4*)gW, out);

    PFN_encodeTiled enc = get_encode_fn();
    CUtensorMap tmA, tmB;
    encode_2d_f16(enc, &tmA, gX, DIN, MROWS, 64, BM);   // box 64x256 (slab width)
    encode_2d_f16(enc, &tmB, gW, DIN, DOUT,  64, BN);   // box 64x192

    static bool attr_set = false;
    if (!attr_set) {
        cudaFuncSetAttribute(gemm_f16_kernel, cudaFuncAttributeMaxDynamicSharedMemorySize,
                             SMEM_TOTAL);
        attr_set = true;
    }

    gemm_f16_kernel<<<GRID, NTHREADS, SMEM_TOTAL>>>(tmA, tmB, out);
}